// round 14
// baseline (speedup 1.0000x reference)
#include <cuda_runtime.h>
#include <cstdint>

#define BB      48
#define NKC     800
#define NMBON   20
#define NFBN    60
#define NDAN    20
#define NREC    100
#define TT      121
#define NSTEP   120
#define W_MAXC  0.05f

#define NTHREADS 512
#define NCTA     (BB * 2)

__device__ float g_rkcT[(long)BB * TT * NKC];
__device__ float g_ifbn[(long)BB * TT * 64];

// ---------------------------------------------------------------------------
// Transpose r_kc [B, NKC, T] -> g_rkcT [B, T, NKC]
// ---------------------------------------------------------------------------
__global__ void transpose_kernel(const float* __restrict__ rkc) {
    __shared__ float tile[32][33];
    const int bz = blockIdx.z;
    const int kt = blockIdx.y;
    const int tt = blockIdx.x;
    const int tx = threadIdx.x, ty = threadIdx.y;

    int k = kt * 32 + ty;
    int t = tt * 32 + tx;
    if (t < TT)
        tile[ty][tx] = rkc[((long)bz * NKC + k) * TT + t];
    __syncthreads();
    int t2 = tt * 32 + ty;
    int k2 = kt * 32 + tx;
    if (t2 < TT)
        g_rkcT[((long)bz * TT + t2) * NKC + k2] = tile[tx][ty];
}

// ---------------------------------------------------------------------------
// Precompute I_fbn(b, t, f) = W_ext[f,0]*e0 + W_ext[f,1]*e1 for all b, t.
// ---------------------------------------------------------------------------
__global__ void ifbn_kernel(const float* __restrict__ r_ext,
                            const float* __restrict__ W_ext) {
    const int b = blockIdx.x;
    const int t = threadIdx.x;
    if (t >= TT) return;
    float e0 = r_ext[((long)b * 2 + 0) * TT + t];
    float e1 = r_ext[((long)b * 2 + 1) * TT + t];
    float* dst = g_ifbn + ((long)b * TT + t) * 64;
#pragma unroll 4
    for (int f = 0; f < NFBN; ++f)
        dst[f] = W_ext[f * 2] * e0 + W_ext[f * 2 + 1] * e1;
}

// ---------------------------------------------------------------------------
// R13 base (279us) + (a) ifbn precomputed to gmem, streamed via the same
// distance-2 cp.async groups as rkc (ring-4) — removes warp 15's per-step
// LDG->ALU chain; (b) DAN dots 2-way j-split: warp 7 rows 80-95 (2 lanes/row)
// + warp 15 lanes 0-7 rows 96-99. Everything else identical.
// ---------------------------------------------------------------------------
// smem floats: mbar 4 | imb 40 | WrM 10000 | rkc4 3200 | r 200 | bias 100 |
//              ifbn 256 (ring 4 x 64) | red 80 | rdan 20 | rbdan 20 | wro 20
#define SM_FLOATS 13940

__global__ __launch_bounds__(NTHREADS, 1) __cluster_dims__(2, 1, 1)
void rnn_kernel(
    const float* __restrict__ r_ext,
    const float* __restrict__ time_arr,
    const float* __restrict__ W_kc0,
    const float* __restrict__ wt0,
    const float* __restrict__ W_recur,
    const float* __restrict__ W_readout,
    const float* __restrict__ bias,
    const float* __restrict__ W_ext,
    float* __restrict__ out)
{
    extern __shared__ float sm[];
    float* mbar_f  = sm;                  // 4
    float* imb     = sm + 4;              // 2 x 20
    float* WrM     = sm + 44;             // 100 x 100 row-major
    float* rkc4    = sm + 10044;          // 4 x 800 ring
    float* r_s     = sm + 13244;          // 2 x 100
    float* bias_s  = sm + 13444;          // 100
    float* ifbn    = sm + 13544;          // 4 x 64 ring (16B aligned)
    float* red_s   = sm + 13800;          // 8 slots x 10 (slot 7 stays 0)
    float* rdan_s  = sm + 13880;          // 20
    float* rbdan_s = sm + 13900;          // 20
    float* wro_s   = sm + 13920;          // 20

    const int tid  = threadIdx.x;
    const int bx   = blockIdx.x;
    const int b    = bx >> 1;
    const int rank = bx & 1;
    const int prank = rank ^ 1;
    const int m_off = rank * 10;
    const int lane = tid & 31;
    const int warp = tid >> 5;
    const int g    = tid >> 8;
    const int q    = tid & 255;
    const bool owner = (q < 200);

    int ci2 = -1;
    bool is_loc = false, is_peer = false;
    if (warp == 7) {
        if (lane < 10)      { ci2 = m_off + lane;            is_loc  = true; }
        else if (lane < 20) { ci2 = (m_off ^ 10) + lane - 10; is_peer = true; }
        else                { ci2 = 20 + (lane - 20); }
    } else if (warp == 15) {
        if (lane < 24) ci2 = 32 + lane;
    } else if (warp == 6) {
        if (lane >= 8 && lane < 20) ci2 = 56 + (lane - 8);
    } else if (warp == 14) {
        if (lane >= 8 && lane < 20) ci2 = 68 + (lane - 8);
    }

    float* out_r  = out;
    float* out_W  = out + (long)TT * BB * NREC;
    float* out_wt = out_W + (long)TT * BB * NMBON * NKC;
    float* out_ro = out_wt + (long)TT * BB * NMBON * NKC;

    const float dt  = time_arr[1] - time_arr[0];
    const float a_r = dt;
    const float a_w = dt * 0.2f;

    const float* rkc_g  = g_rkcT + (long)b * TT * NKC;
    const float* ifbn_g = g_ifbn + (long)b * TT * 64;

    const uint32_t imb_loc  = (uint32_t)__cvta_generic_to_shared(imb);
    const uint32_t mbar_loc = (uint32_t)__cvta_generic_to_shared(mbar_f);
    uint32_t imb_rem, mbar_rem;
    asm("mapa.shared::cluster.u32 %0, %1, %2;" : "=r"(imb_rem)  : "r"(imb_loc),  "r"(prank));
    asm("mapa.shared::cluster.u32 %0, %1, %2;" : "=r"(mbar_rem) : "r"(mbar_loc), "r"(prank));

    // ---------------- init ----------------
    if (tid == 0) {
        asm volatile("mbarrier.init.shared.b64 [%0], 10;" :: "r"(mbar_loc)     : "memory");
        asm volatile("mbarrier.init.shared.b64 [%0], 10;" :: "r"(mbar_loc + 8) : "memory");
    }
    for (int idx = tid; idx < NREC * NREC; idx += NTHREADS) {
        int i = idx / NREC, j = idx % NREC;
        float v = W_recur[idx];
        if (i < NMBON && j >= NREC - NDAN) v = 0.f;
        WrM[idx] = v;
    }
    if (tid < 80)       red_s[tid] = 0.f;
    if (tid < NREC)     bias_s[tid] = bias[tid];
    if (tid < NMBON)    wro_s[tid]  = W_readout[tid];
    if (tid >= 128 && tid < 192) ifbn[tid - 128] = ifbn_g[tid - 128];  // slot 0 = ifbn(0)
    if (tid < NREC) {
        float r0 = (tid < NMBON) ? 0.f : 0.1f;
        r_s[tid] = r0;
        if (rank == 0) out_r[(long)b * NREC + tid] = r0;
    }
    if (tid < NDAN) rbdan_s[tid] = 0.1f;
    for (int k = tid; k < NKC; k += NTHREADS)
        rkc4[k] = rkc_g[k];               // slot 0 = rkc(0)
    if (tid == 0 && rank == 0) out_ro[b] = 0.f;

    // owner state: W, wt, rb_kc (registers)
    float4 Wv[5], wtv[5], bkv;
    if (owner) {
        const long ibase = ((long)b * NMBON + m_off + g * 5) * NKC + q * 4;
        const long obase = ((long)b) * (NMBON * NKC) + (long)(m_off + g * 5) * NKC + q * 4;
#pragma unroll
        for (int mm = 0; mm < 5; ++mm) {
            float4 w  = *(const float4*)(W_kc0 + ibase + (long)mm * NKC);
            float4 wt = *(const float4*)(wt0   + ibase + (long)mm * NKC);
            Wv[mm] = w; wtv[mm] = wt;
            *(float4*)(out_W  + obase + (long)mm * NKC) = w;
            *(float4*)(out_wt + obase + (long)mm * NKC) = wt;
        }
        bkv = *(const float4*)(rkc_g + q * 4);   // rb_kc(-1) = rkc(:,0)
    } else {
#pragma unroll
        for (int mm = 0; mm < 5; ++mm) {
            Wv[mm]  = make_float4(0.f, 0.f, 0.f, 0.f);
            wtv[mm] = Wv[mm];
        }
        bkv = make_float4(0.f, 0.f, 0.f, 0.f);
    }
    float rb_reg = 0.1f;                  // rbdan register carry (DAN h==0 lanes)

    // preloop prefetch: rkc(1) + ifbn(1) -> slot 1 (one committed group)
    if (warp == 15) {
        const float* gsrc = rkc_g + (long)1 * NKC;
#pragma unroll
        for (int j = 0; j < 7; ++j) {
            int c = lane + 32 * j;
            if (c < 200) {
                uint32_t dst = (uint32_t)__cvta_generic_to_shared(rkc4 + 800 + c * 4);
                asm volatile("cp.async.cg.shared.global [%0], [%1], 16;\n"
                             :: "r"(dst), "l"(gsrc + c * 4));
            }
        }
        if (lane < 16) {
            uint32_t dst = (uint32_t)__cvta_generic_to_shared(ifbn + 64 + lane * 4);
            asm volatile("cp.async.cg.shared.global [%0], [%1], 16;\n"
                         :: "r"(dst), "l"(ifbn_g + 64 + lane * 4));
        }
        asm volatile("cp.async.commit_group;\n" ::: "memory");
    }
    __syncthreads();
    asm volatile("barrier.cluster.arrive.aligned;" ::: "memory");
    asm volatile("barrier.cluster.wait.aligned;"   ::: "memory");

    // ---------------- time loop ----------------
    for (int t = 0; t < NSTEP; ++t) {
        const int s0  = t & 3;            // ring slot for rkc(t)/ifbn(t)
        const int hb  = t & 1;
        const int par = (t >> 1) & 1;

        const float* rc = r_s + hb * NREC;
        float* rn_buf   = r_s + (hb ^ 1) * NREC;

        // pre-bar1: B ∥ DAN rows 80-95 (warp7 2-way) ∥ prefetch + DAN 96-99 + readout (warp15)
        if ((warp & 7) != 7) {
            float4 kc = make_float4(0.f, 0.f, 0.f, 0.f);
            if (owner) kc = *(const float4*)(rkc4 + s0 * 800 + q * 4);
#pragma unroll
            for (int mm = 0; mm < 5; ++mm) {
                float4 w = Wv[mm];
                float p = w.x * kc.x + w.y * kc.y + w.z * kc.z + w.w * kc.w;
                p += __shfl_xor_sync(0xffffffffu, p, 16);
                p += __shfl_xor_sync(0xffffffffu, p, 8);
                p += __shfl_xor_sync(0xffffffffu, p, 4);
                p += __shfl_xor_sync(0xffffffffu, p, 2);
                p += __shfl_xor_sync(0xffffffffu, p, 1);
                if (lane == 0)
                    red_s[(warp & 7) * 10 + g * 5 + mm] = p;
            }
        } else if (warp == 7) {
            // DAN rows 80-95, 2-way j-split (row = 80 + lane/2, h = lane&1)
            const int row = 80 + (lane >> 1);
            const int h   = lane & 1;
            const float4* wrow = (const float4*)(WrM + row * NREC);
            const float4* r4   = (const float4*)rc;
            float a0 = 0.f, a1 = 0.f;
            const int base = h * 13;
#pragma unroll
            for (int jb = 0; jb < 13; ++jb) {
                int j = base + jb;
                if (j < 25) {
                    float4 wv = wrow[j];
                    float4 rv = r4[j];
                    a0 = fmaf(wv.x, rv.x, a0);
                    a1 = fmaf(wv.y, rv.y, a1);
                    a0 = fmaf(wv.z, rv.z, a0);
                    a1 = fmaf(wv.w, rv.w, a1);
                }
            }
            float p = a0 + a1;
            p += __shfl_xor_sync(0xffffffffu, p, 1);
            if (h == 0) {
                float pre  = p + bias_s[row];
                float relu = fmaxf(pre, 0.f);
                float rold = rc[row];
                float rn   = fmaf(a_r, relu - rold, rold);
                rn_buf[row] = rn;
                if (rank == 0) out_r[((long)(t + 1) * BB + b) * NREC + row] = rn;
                rdan_s[row - 80] = rn;
                rb_reg = fmaf(a_w, rn - rb_reg, rb_reg);
                rbdan_s[row - 80] = rb_reg;
            }
        } else {
            // warp 15: distance-2 prefetch rkc(t+2)+ifbn(t+2); DAN 96-99; readout
            if (t + 2 <= NSTEP - 1) {
                const float* gsrc = rkc_g + (long)(t + 2) * NKC;
                const int sw = (t + 2) & 3;
#pragma unroll
                for (int j = 0; j < 7; ++j) {
                    int c = lane + 32 * j;
                    if (c < 200) {
                        uint32_t dst = (uint32_t)__cvta_generic_to_shared(rkc4 + sw * 800 + c * 4);
                        asm volatile("cp.async.cg.shared.global [%0], [%1], 16;\n"
                                     :: "r"(dst), "l"(gsrc + c * 4));
                    }
                }
                if (lane < 16) {
                    uint32_t dst = (uint32_t)__cvta_generic_to_shared(ifbn + sw * 64 + lane * 4);
                    asm volatile("cp.async.cg.shared.global [%0], [%1], 16;\n"
                                 :: "r"(dst), "l"(ifbn_g + (long)(t + 2) * 64 + lane * 4));
                }
            }
            asm volatile("cp.async.commit_group;\n" ::: "memory");   // possibly empty
            if (lane < 8) {
                // DAN rows 96-99, 2-way j-split
                const int row = 96 + (lane >> 1);
                const int h   = lane & 1;
                const float4* wrow = (const float4*)(WrM + row * NREC);
                const float4* r4   = (const float4*)rc;
                float a0 = 0.f, a1 = 0.f;
                const int base = h * 13;
#pragma unroll
                for (int jb = 0; jb < 13; ++jb) {
                    int j = base + jb;
                    if (j < 25) {
                        float4 wv = wrow[j];
                        float4 rv = r4[j];
                        a0 = fmaf(wv.x, rv.x, a0);
                        a1 = fmaf(wv.y, rv.y, a1);
                        a0 = fmaf(wv.z, rv.z, a0);
                        a1 = fmaf(wv.w, rv.w, a1);
                    }
                }
                float p = a0 + a1;
                p += __shfl_xor_sync(0xFFu, p, 1);
                if (h == 0) {
                    float pre  = p + bias_s[row];
                    float relu = fmaxf(pre, 0.f);
                    float rold = rc[row];
                    float rn   = fmaf(a_r, relu - rold, rold);
                    rn_buf[row] = rn;
                    if (rank == 0) out_r[((long)(t + 1) * BB + b) * NREC + row] = rn;
                    rdan_s[row - 80] = rn;
                    rb_reg = fmaf(a_w, rn - rb_reg, rb_reg);
                    rbdan_s[row - 80] = rb_reg;
                }
            } else if (lane == 24 && rank == 0 && t > 0) {
                // readout(t) from r(t); out_ro[0] written in init (= 0)
                float v = 0.f;
#pragma unroll
                for (int m = 0; m < NMBON; ++m)
                    v = fmaf(rc[m], wro_s[m], v);
                out_ro[(long)t * BB + b] = v;
            }
        }
        __syncthreads();   // bar1: red_s, rdan/rbdan(t) ready

        // post-bar1: send FIRST, then D (owners) ∥ C dots ∥ cp wait
        float vloc = 0.f;
        if (warp == 7 && lane < 10) {
            vloc = red_s[0 * 10 + lane] + red_s[1 * 10 + lane] + red_s[2 * 10 + lane]
                 + red_s[3 * 10 + lane] + red_s[4 * 10 + lane] + red_s[5 * 10 + lane]
                 + red_s[6 * 10 + lane];
            asm volatile("st.shared::cluster.f32 [%0], %1;"
                         :: "r"(imb_rem + (hb * 20 + m_off + lane) * 4), "f"(vloc) : "memory");
            asm volatile("mbarrier.arrive.release.cluster.shared::cluster.b64 _, [%0];"
                         :: "r"(mbar_rem + hb * 8) : "memory");
        }

        if (owner) {
            // D(t): rb_kc EMA in registers + plasticity + streaming stores
            float4 kc = *(const float4*)(rkc4 + s0 * 800 + q * 4);
            bkv.x = fmaf(a_w, kc.x - bkv.x, bkv.x);
            bkv.y = fmaf(a_w, kc.y - bkv.y, bkv.y);
            bkv.z = fmaf(a_w, kc.z - bkv.z, bkv.z);
            bkv.w = fmaf(a_w, kc.w - bkv.w, bkv.w);
            const long obase = ((long)(t + 1) * BB + b) * (NMBON * NKC)
                             + (long)(m_off + g * 5) * NKC + q * 4;
#pragma unroll
            for (int mm = 0; mm < 5; ++mm) {
                const int m = m_off + g * 5 + mm;
                const float rbd = rbdan_s[m];
                const float rd  = rdan_s[m];
                float4 w = Wv[mm], wt = wtv[mm];
                float dw;
                dw = fmaf(rbd, kc.x, -(rd * bkv.x)); wt.x = fmaf(dw, dt, wt.x);
                dw = fmaf(rbd, kc.y, -(rd * bkv.y)); wt.y = fmaf(dw, dt, wt.y);
                dw = fmaf(rbd, kc.z, -(rd * bkv.z)); wt.z = fmaf(dw, dt, wt.z);
                dw = fmaf(rbd, kc.w, -(rd * bkv.w)); wt.w = fmaf(dw, dt, wt.w);
                w.x = fminf(fmaxf(fmaf(a_w, wt.x - w.x, w.x), 0.f), W_MAXC);
                w.y = fminf(fmaxf(fmaf(a_w, wt.y - w.y, w.y), 0.f), W_MAXC);
                w.z = fminf(fmaxf(fmaf(a_w, wt.z - w.z, w.z), 0.f), W_MAXC);
                w.w = fminf(fmaxf(fmaf(a_w, wt.w - w.w, w.w), 0.f), W_MAXC);
                Wv[mm] = w; wtv[mm] = wt;
                *(float4*)(out_W  + obase + (long)mm * NKC) = w;
                *(float4*)(out_wt + obase + (long)mm * NKC) = wt;
            }
        }

        if (ci2 >= 0) {
            const int i = ci2;
            const float4* wrow = (const float4*)(WrM + i * NREC);
            const float4* r4   = (const float4*)rc;
            float a0 = 0.f, a1 = 0.f, a2 = 0.f, a3 = 0.f;
#pragma unroll
            for (int jb = 0; jb < 25; ++jb) {
                float4 wv = wrow[jb];
                float4 rv = r4[jb];
                a0 = fmaf(wv.x, rv.x, a0);
                a1 = fmaf(wv.y, rv.y, a1);
                a2 = fmaf(wv.z, rv.z, a2);
                a3 = fmaf(wv.w, rv.w, a3);
            }
            float p = (a0 + a1) + (a2 + a3);
            float itot;
            if (is_loc) {
                itot = vloc;
            } else if (is_peer) {
                uint32_t done;
                asm volatile(
                    "{\n\t.reg .pred p;\n\t"
                    "mbarrier.try_wait.parity.acquire.cluster.shared::cta.b64 p, [%1], %2;\n\t"
                    "selp.b32 %0, 1, 0, p;\n\t}"
                    : "=r"(done) : "r"(mbar_loc + hb * 8), "r"(par) : "memory");
                while (!done) {
                    asm volatile(
                        "{\n\t.reg .pred p;\n\t"
                        "mbarrier.try_wait.parity.acquire.cluster.shared::cta.b64 p, [%1], %2, 0x989680;\n\t"
                        "selp.b32 %0, 1, 0, p;\n\t}"
                        : "=r"(done) : "r"(mbar_loc + hb * 8), "r"(par) : "memory");
                }
                itot = imb[hb * 20 + i];
            } else {
                itot = ifbn[s0 * 64 + (i - NMBON)];
            }
            float pre  = p + bias_s[i] + itot;
            float relu = fmaxf(pre, 0.f);
            float rold = rc[i];
            float rn   = fmaf(a_r, relu - rold, rold);
            rn_buf[i] = rn;
            if (rank == 0) out_r[((long)(t + 1) * BB + b) * NREC + i] = rn;
        }

        if (warp == 15)
            asm volatile("cp.async.wait_group 1;\n" ::: "memory");   // rkc/ifbn(t+1) ready

        __syncthreads();   // bar2
    }

    // final readout: r(120) is in buffer 0
    if (warp == 15 && lane == 24 && rank == 0) {
        float v = 0.f;
#pragma unroll
        for (int m = 0; m < NMBON; ++m)
            v = fmaf(r_s[m], wro_s[m], v);
        out_ro[(long)NSTEP * BB + b] = v;
    }

    asm volatile("barrier.cluster.arrive.aligned;" ::: "memory");
    asm volatile("barrier.cluster.wait.aligned;"   ::: "memory");
}

// ---------------------------------------------------------------------------
extern "C" void kernel_launch(void* const* d_in, const int* in_sizes, int n_in,
                              void* d_out, int out_size) {
    const float* r_kc      = (const float*)d_in[0];
    const float* r_ext     = (const float*)d_in[1];
    const float* time_arr  = (const float*)d_in[2];
    const float* W_kc0     = (const float*)d_in[3];
    const float* wt0       = (const float*)d_in[4];
    const float* W_recur   = (const float*)d_in[5];
    const float* W_readout = (const float*)d_in[6];
    const float* bias      = (const float*)d_in[7];
    const float* W_ext     = (const float*)d_in[8];
    float* out = (float*)d_out;

    cudaFuncSetAttribute(rnn_kernel, cudaFuncAttributeMaxDynamicSharedMemorySize,
                         SM_FLOATS * (int)sizeof(float));

    transpose_kernel<<<dim3(4, 25, BB), dim3(32, 32)>>>(r_kc);
    ifbn_kernel<<<BB, 128>>>(r_ext, W_ext);
    rnn_kernel<<<NCTA, NTHREADS, SM_FLOATS * (int)sizeof(float)>>>(
        r_ext, time_arr, W_kc0, wt0, W_recur, W_readout, bias, W_ext, out);
}

// round 15
// speedup vs baseline: 1.0428x; 1.0428x over previous
#include <cuda_runtime.h>
#include <cstdint>

#define BB      48
#define NKC     800
#define NMBON   20
#define NFBN    60
#define NDAN    20
#define NREC    100
#define TT      121
#define NSTEP   120
#define W_MAXC  0.05f

#define NTHREADS 512
#define NCTA     (BB * 2)

__device__ float g_rkcT[(long)BB * TT * NKC];

// ---------------------------------------------------------------------------
// Transpose r_kc [B, NKC, T] -> g_rkcT [B, T, NKC]
// ---------------------------------------------------------------------------
__global__ void transpose_kernel(const float* __restrict__ rkc) {
    __shared__ float tile[32][33];
    const int bz = blockIdx.z;
    const int kt = blockIdx.y;
    const int tt = blockIdx.x;
    const int tx = threadIdx.x, ty = threadIdx.y;

    int k = kt * 32 + ty;
    int t = tt * 32 + tx;
    if (t < TT)
        tile[ty][tx] = rkc[((long)bz * NKC + k) * TT + t];
    __syncthreads();
    int t2 = tt * 32 + ty;
    int k2 = kt * 32 + tx;
    if (t2 < TT)
        g_rkcT[((long)bz * TT + t2) * NKC + k2] = tile[tx][ty];
}

// ---------------------------------------------------------------------------
// R11 structure EXACT (best: 279us) + loop-carried pointer addressing:
// all per-step 64-bit index chains replaced by pointer increments; wrow and
// exchange addresses hoisted. No sync/numerics changes.
// ---------------------------------------------------------------------------
// smem floats: mbar 4 | imb 40 | WrM 10000 | rkc4 3200 | r 200 | bias 100 |
//              ifbn 128 | red 80 | rdan 20 | rbdan 20 | wro 20 | wext 120
#define SM_FLOATS (4 + 40 + 10000 + 3200 + 200 + 100 + 128 + 80 + 20 + 20 + 20 + 120)

#define WSTRIDE ((long)BB * NMBON * NKC)   // out_W/out_wt per-t stride
#define RSTRIDE ((long)BB * NREC)          // out_r per-t stride

__global__ __launch_bounds__(NTHREADS, 1) __cluster_dims__(2, 1, 1)
void rnn_kernel(
    const float* __restrict__ r_ext,
    const float* __restrict__ time_arr,
    const float* __restrict__ W_kc0,
    const float* __restrict__ wt0,
    const float* __restrict__ W_recur,
    const float* __restrict__ W_readout,
    const float* __restrict__ bias,
    const float* __restrict__ W_ext,
    float* __restrict__ out)
{
    extern __shared__ float sm[];
    float* mbar_f  = sm;                  // 4
    float* imb     = sm + 4;              // 2 x 20
    float* WrM     = sm + 44;             // 100 x 100 row-major
    float* rkc4    = sm + 10044;          // 4 x 800 ring
    float* r_s     = sm + 13244;          // 2 x 100
    float* bias_s  = sm + 13444;          // 100
    float* ifbn    = sm + 13544;          // 2 x 64
    float* red_s   = sm + 13672;          // 8 slots x 10 (slot 7 stays 0)
    float* rdan_s  = sm + 13752;          // 20
    float* rbdan_s = sm + 13772;          // 20
    float* wro_s   = sm + 13792;          // 20
    float* wext_s  = sm + 13812;          // 120

    const int tid  = threadIdx.x;
    const int bx   = blockIdx.x;
    const int b    = bx >> 1;
    const int rank = bx & 1;
    const int prank = rank ^ 1;
    const int m_off = rank * 10;
    const int lane = tid & 31;
    const int warp = tid >> 5;
    const int g    = tid >> 8;
    const int q    = tid & 255;
    const bool owner = (q < 200);

    int ci2 = -1;
    bool is_loc = false, is_peer = false;
    if (warp == 7) {
        if (lane < 10)      { ci2 = m_off + lane;            is_loc  = true; }
        else if (lane < 20) { ci2 = (m_off ^ 10) + lane - 10; is_peer = true; }
        else                { ci2 = 20 + (lane - 20); }
    } else if (warp == 15) {
        if (lane < 24) ci2 = 32 + lane;
    } else if (warp == 6) {
        if (lane >= 8 && lane < 20) ci2 = 56 + (lane - 8);
    } else if (warp == 14) {
        if (lane >= 8 && lane < 20) ci2 = 68 + (lane - 8);
    }

    float* out_r  = out;
    float* out_W  = out + (long)TT * BB * NREC;
    float* out_wt = out_W + (long)TT * BB * NMBON * NKC;
    float* out_ro = out_wt + (long)TT * BB * NMBON * NKC;

    const float dt  = time_arr[1] - time_arr[0];
    const float a_r = dt;
    const float a_w = dt * 0.2f;

    const float* rkc_g = g_rkcT + (long)b * TT * NKC;

    const uint32_t imb_loc  = (uint32_t)__cvta_generic_to_shared(imb);
    const uint32_t mbar_loc = (uint32_t)__cvta_generic_to_shared(mbar_f);
    uint32_t imb_rem, mbar_rem;
    asm("mapa.shared::cluster.u32 %0, %1, %2;" : "=r"(imb_rem)  : "r"(imb_loc),  "r"(prank));
    asm("mapa.shared::cluster.u32 %0, %1, %2;" : "=r"(mbar_rem) : "r"(mbar_loc), "r"(prank));

    // ---------------- init ----------------
    if (tid == 0) {
        asm volatile("mbarrier.init.shared.b64 [%0], 10;" :: "r"(mbar_loc)     : "memory");
        asm volatile("mbarrier.init.shared.b64 [%0], 10;" :: "r"(mbar_loc + 8) : "memory");
    }
    for (int idx = tid; idx < NREC * NREC; idx += NTHREADS) {
        int i = idx / NREC, j = idx % NREC;
        float v = W_recur[idx];
        if (i < NMBON && j >= NREC - NDAN) v = 0.f;
        WrM[idx] = v;
    }
    if (tid < 80)       red_s[tid] = 0.f;
    if (tid < NREC)     bias_s[tid] = bias[tid];
    if (tid < NMBON)    wro_s[tid]  = W_readout[tid];
    if (tid >= 128 && tid < 128 + NFBN * 2) wext_s[tid - 128] = W_ext[tid - 128];
    if (tid < NREC) {
        float r0 = (tid < NMBON) ? 0.f : 0.1f;
        r_s[tid] = r0;
        if (rank == 0) out_r[(long)b * NREC + tid] = r0;
    }
    if (tid < NDAN) rbdan_s[tid] = 0.1f;
    for (int k = tid; k < NKC; k += NTHREADS)
        rkc4[k] = rkc_g[k];               // slot 0 = rkc(0)
    __syncthreads();                      // wext ready
    if (tid < NFBN) {
        float e0 = r_ext[((long)b * 2 + 0) * TT];
        float e1 = r_ext[((long)b * 2 + 1) * TT];
        ifbn[tid] = wext_s[tid * 2] * e0 + wext_s[tid * 2 + 1] * e1;
    }
    if (tid == 0 && rank == 0) out_ro[b] = 0.f;

    // owner state: W, wt, rb_kc (registers)
    float4 Wv[5], wtv[5], bkv;
    if (owner) {
        const long ibase = ((long)b * NMBON + m_off + g * 5) * NKC + q * 4;
        const long obase = ((long)b) * (NMBON * NKC) + (long)(m_off + g * 5) * NKC + q * 4;
#pragma unroll
        for (int mm = 0; mm < 5; ++mm) {
            float4 w  = *(const float4*)(W_kc0 + ibase + (long)mm * NKC);
            float4 wt = *(const float4*)(wt0   + ibase + (long)mm * NKC);
            Wv[mm] = w; wtv[mm] = wt;
            *(float4*)(out_W  + obase + (long)mm * NKC) = w;
            *(float4*)(out_wt + obase + (long)mm * NKC) = wt;
        }
        bkv = *(const float4*)(rkc_g + q * 4);   // rb_kc(-1) = rkc(:,0)
    } else {
#pragma unroll
        for (int mm = 0; mm < 5; ++mm) {
            Wv[mm]  = make_float4(0.f, 0.f, 0.f, 0.f);
            wtv[mm] = Wv[mm];
        }
        bkv = make_float4(0.f, 0.f, 0.f, 0.f);
    }

    // ---- loop-carried pointers (strength reduction) ----
    // owner output base for t=1:
    float* pW  = out_W  + WSTRIDE + (long)b * (NMBON * NKC) + (long)(m_off + g * 5) * NKC + q * 4;
    float* pwt = out_wt + WSTRIDE + (long)b * (NMBON * NKC) + (long)(m_off + g * 5) * NKC + q * 4;
    // r output base for t=1 (used by dot threads + DAN):
    float* pr  = out_r + RSTRIDE + (long)b * NREC;
    // readout base for t=1:
    float* pro = out_ro + BB + b;
    // prefetch source pointer (rkc(t+2), first used at t=0 -> rkc(2)):
    const float* gsrc_p = rkc_g + 2L * NKC;
    // r_ext pointers for t+1 (first used at t=0 -> index 1):
    const float* pe0 = r_ext + ((long)b * 2 + 0) * TT + 1;
    const float* pe1 = r_ext + ((long)b * 2 + 1) * TT + 1;
    // hoisted dot row pointer (t-invariant):
    const float4* wrow = (ci2 >= 0) ? (const float4*)(WrM + ci2 * NREC) : (const float4*)WrM;

    // preloop prefetch: rkc(1) -> slot 1 (one committed group)
    if (warp == 15) {
        const float* gsrc = rkc_g + (long)1 * NKC;
#pragma unroll
        for (int j = 0; j < 7; ++j) {
            int c = lane + 32 * j;
            if (c < 200) {
                uint32_t dst = (uint32_t)__cvta_generic_to_shared(rkc4 + 800 + c * 4);
                asm volatile("cp.async.cg.shared.global [%0], [%1], 16;\n"
                             :: "r"(dst), "l"(gsrc + c * 4));
            }
        }
        asm volatile("cp.async.commit_group;\n" ::: "memory");
    }
    __syncthreads();
    asm volatile("barrier.cluster.arrive.aligned;" ::: "memory");
    asm volatile("barrier.cluster.wait.aligned;"   ::: "memory");

    // ---------------- time loop ----------------
    for (int t = 0; t < NSTEP; ++t) {
        const int s0  = t & 3;            // ring slot for rkc(t)
        const int hb  = t & 1;
        const int par = (t >> 1) & 1;

        const float* rc = r_s + hb * NREC;
        float* rn_buf   = r_s + (hb ^ 1) * NREC;
        const float* rkc_cur = rkc4 + s0 * 800;

        // pre-bar1: B ∥ DAN-C (warp7) ∥ prefetch+ifbn (warp15)
        if ((warp & 7) != 7) {
            float4 kc = make_float4(0.f, 0.f, 0.f, 0.f);
            if (owner) kc = *(const float4*)(rkc_cur + q * 4);
#pragma unroll
            for (int mm = 0; mm < 5; ++mm) {
                float4 w = Wv[mm];
                float p = w.x * kc.x + w.y * kc.y + w.z * kc.z + w.w * kc.w;
                p += __shfl_xor_sync(0xffffffffu, p, 16);
                p += __shfl_xor_sync(0xffffffffu, p, 8);
                p += __shfl_xor_sync(0xffffffffu, p, 4);
                p += __shfl_xor_sync(0xffffffffu, p, 2);
                p += __shfl_xor_sync(0xffffffffu, p, 1);
                if (lane == 0)
                    red_s[(warp & 7) * 10 + g * 5 + mm] = p;
            }
        } else if (warp == 7) {
            if (lane < NDAN) {
                const int i = 80 + lane;
                const float4* wrow7 = (const float4*)(WrM + i * NREC);   // hoistable but warp7-only
                const float4* r4    = (const float4*)rc;
                float a0 = 0.f, a1 = 0.f, a2 = 0.f, a3 = 0.f;
#pragma unroll
                for (int jb = 0; jb < 25; ++jb) {
                    float4 wv = wrow7[jb];
                    float4 rv = r4[jb];
                    a0 = fmaf(wv.x, rv.x, a0);
                    a1 = fmaf(wv.y, rv.y, a1);
                    a2 = fmaf(wv.z, rv.z, a2);
                    a3 = fmaf(wv.w, rv.w, a3);
                }
                float pre  = (a0 + a1) + (a2 + a3) + bias_s[i];
                float relu = fmaxf(pre, 0.f);
                float rold = rc[i];
                float rn   = fmaf(a_r, relu - rold, rold);
                rn_buf[i] = rn;
                if (rank == 0) pr[i] = rn;
                rdan_s[lane] = rn;
                float rb = rbdan_s[lane];
                rbdan_s[lane] = fmaf(a_w, rn - rb, rb);
            }
        } else {
            // warp 15: distance-2 prefetch rkc(t+2), ifbn(t+1)
            if (t + 2 <= NSTEP - 1) {
                const int sw = (t + 2) & 3;
                float* dstbase = rkc4 + sw * 800;
#pragma unroll
                for (int j = 0; j < 7; ++j) {
                    int c = lane + 32 * j;
                    if (c < 200) {
                        uint32_t dst = (uint32_t)__cvta_generic_to_shared(dstbase + c * 4);
                        asm volatile("cp.async.cg.shared.global [%0], [%1], 16;\n"
                                     :: "r"(dst), "l"(gsrc_p + c * 4));
                    }
                }
            }
            asm volatile("cp.async.commit_group;\n" ::: "memory");   // possibly empty
            float e0 = *pe0;
            float e1 = *pe1;
            {
                int f = lane;
                ifbn[(hb ^ 1) * 64 + f] = wext_s[f * 2] * e0 + wext_s[f * 2 + 1] * e1;
                f = lane + 32;
                if (f < NFBN)
                    ifbn[(hb ^ 1) * 64 + f] = wext_s[f * 2] * e0 + wext_s[f * 2 + 1] * e1;
            }
        }
        __syncthreads();   // bar1: red_s, rdan/rbdan(t), ifbn(t+1) ready

        // post-bar1: send FIRST, then D (owners) ∥ C dots ∥ cp wait
        float vloc = 0.f;
        if (warp == 7 && lane < 10) {
            vloc = red_s[0 * 10 + lane] + red_s[1 * 10 + lane] + red_s[2 * 10 + lane]
                 + red_s[3 * 10 + lane] + red_s[4 * 10 + lane] + red_s[5 * 10 + lane]
                 + red_s[6 * 10 + lane];
            asm volatile("st.shared::cluster.f32 [%0], %1;"
                         :: "r"(imb_rem + (hb * 20 + m_off + lane) * 4), "f"(vloc) : "memory");
            asm volatile("mbarrier.arrive.release.cluster.shared::cluster.b64 _, [%0];"
                         :: "r"(mbar_rem + hb * 8) : "memory");
        }

        if (owner) {
            // D(t): rb_kc EMA in registers + plasticity + streaming stores
            float4 kc = *(const float4*)(rkc_cur + q * 4);
            bkv.x = fmaf(a_w, kc.x - bkv.x, bkv.x);
            bkv.y = fmaf(a_w, kc.y - bkv.y, bkv.y);
            bkv.z = fmaf(a_w, kc.z - bkv.z, bkv.z);
            bkv.w = fmaf(a_w, kc.w - bkv.w, bkv.w);
#pragma unroll
            for (int mm = 0; mm < 5; ++mm) {
                const int m = m_off + g * 5 + mm;
                const float rbd = rbdan_s[m];
                const float rd  = rdan_s[m];
                float4 w = Wv[mm], wt = wtv[mm];
                float dw;
                dw = fmaf(rbd, kc.x, -(rd * bkv.x)); wt.x = fmaf(dw, dt, wt.x);
                dw = fmaf(rbd, kc.y, -(rd * bkv.y)); wt.y = fmaf(dw, dt, wt.y);
                dw = fmaf(rbd, kc.z, -(rd * bkv.z)); wt.z = fmaf(dw, dt, wt.z);
                dw = fmaf(rbd, kc.w, -(rd * bkv.w)); wt.w = fmaf(dw, dt, wt.w);
                w.x = fminf(fmaxf(fmaf(a_w, wt.x - w.x, w.x), 0.f), W_MAXC);
                w.y = fminf(fmaxf(fmaf(a_w, wt.y - w.y, w.y), 0.f), W_MAXC);
                w.z = fminf(fmaxf(fmaf(a_w, wt.z - w.z, w.z), 0.f), W_MAXC);
                w.w = fminf(fmaxf(fmaf(a_w, wt.w - w.w, w.w), 0.f), W_MAXC);
                Wv[mm] = w; wtv[mm] = wt;
                *(float4*)(pW  + (long)mm * NKC) = w;
                *(float4*)(pwt + (long)mm * NKC) = wt;
            }
        }

        if (ci2 >= 0) {
            const int i = ci2;
            const float4* r4 = (const float4*)rc;
            float a0 = 0.f, a1 = 0.f, a2 = 0.f, a3 = 0.f;
#pragma unroll
            for (int jb = 0; jb < 25; ++jb) {
                float4 wv = wrow[jb];
                float4 rv = r4[jb];
                a0 = fmaf(wv.x, rv.x, a0);
                a1 = fmaf(wv.y, rv.y, a1);
                a2 = fmaf(wv.z, rv.z, a2);
                a3 = fmaf(wv.w, rv.w, a3);
            }
            float p = (a0 + a1) + (a2 + a3);
            float itot;
            if (is_loc) {
                itot = vloc;
            } else if (is_peer) {
                uint32_t done;
                asm volatile(
                    "{\n\t.reg .pred p;\n\t"
                    "mbarrier.try_wait.parity.acquire.cluster.shared::cta.b64 p, [%1], %2;\n\t"
                    "selp.b32 %0, 1, 0, p;\n\t}"
                    : "=r"(done) : "r"(mbar_loc + hb * 8), "r"(par) : "memory");
                while (!done) {
                    asm volatile(
                        "{\n\t.reg .pred p;\n\t"
                        "mbarrier.try_wait.parity.acquire.cluster.shared::cta.b64 p, [%1], %2, 0x989680;\n\t"
                        "selp.b32 %0, 1, 0, p;\n\t}"
                        : "=r"(done) : "r"(mbar_loc + hb * 8), "r"(par) : "memory");
                }
                itot = imb[hb * 20 + i];
            } else {
                itot = ifbn[hb * 64 + (i - NMBON)];
            }
            float pre  = p + bias_s[i] + itot;
            float relu = fmaxf(pre, 0.f);
            float rold = rc[i];
            float rn   = fmaf(a_r, relu - rold, rold);
            rn_buf[i] = rn;
            if (rank == 0) pr[i] = rn;
        }

        if (warp == 15)
            asm volatile("cp.async.wait_group 1;\n" ::: "memory");   // rkc(t+1) ready

        __syncthreads();   // bar2

        if (warp == 0 && rank == 0) {
            float v = (lane < NMBON) ? rn_buf[lane] * wro_s[lane] : 0.f;
            v += __shfl_xor_sync(0xffffffffu, v, 16);
            v += __shfl_xor_sync(0xffffffffu, v, 8);
            v += __shfl_xor_sync(0xffffffffu, v, 4);
            v += __shfl_xor_sync(0xffffffffu, v, 2);
            v += __shfl_xor_sync(0xffffffffu, v, 1);
            if (lane == 0) *pro = v;
        }

        // advance loop-carried pointers
        pW  += WSTRIDE;
        pwt += WSTRIDE;
        pr  += RSTRIDE;
        pro += BB;
        gsrc_p += NKC;
        ++pe0; ++pe1;
    }

    asm volatile("barrier.cluster.arrive.aligned;" ::: "memory");
    asm volatile("barrier.cluster.wait.aligned;"   ::: "memory");
}

// ---------------------------------------------------------------------------
extern "C" void kernel_launch(void* const* d_in, const int* in_sizes, int n_in,
                              void* d_out, int out_size) {
    const float* r_kc      = (const float*)d_in[0];
    const float* r_ext     = (const float*)d_in[1];
    const float* time_arr  = (const float*)d_in[2];
    const float* W_kc0     = (const float*)d_in[3];
    const float* wt0       = (const float*)d_in[4];
    const float* W_recur   = (const float*)d_in[5];
    const float* W_readout = (const float*)d_in[6];
    const float* bias      = (const float*)d_in[7];
    const float* W_ext     = (const float*)d_in[8];
    float* out = (float*)d_out;

    cudaFuncSetAttribute(rnn_kernel, cudaFuncAttributeMaxDynamicSharedMemorySize,
                         SM_FLOATS * (int)sizeof(float));

    transpose_kernel<<<dim3(4, 25, BB), dim3(32, 32)>>>(r_kc);
    rnn_kernel<<<NCTA, NTHREADS, SM_FLOATS * (int)sizeof(float)>>>(
        r_ext, time_arr, W_kc0, wt0, W_recur, W_readout, bias, W_ext, out);
}

// round 16
// speedup vs baseline: 1.0540x; 1.0107x over previous
#include <cuda_runtime.h>
#include <cstdint>

#define BB      48
#define NKC     800
#define NMBON   20
#define NFBN    60
#define NDAN    20
#define NREC    100
#define TT      121
#define NSTEP   120
#define W_MAXC  0.05f

#define NTHREADS 512
#define NCTA     (BB * 2)

__device__ float g_rkcT[(long)BB * TT * NKC];

// ---------------------------------------------------------------------------
// Transpose r_kc [B, NKC, T] -> g_rkcT [B, T, NKC]
// ---------------------------------------------------------------------------
__global__ void transpose_kernel(const float* __restrict__ rkc) {
    __shared__ float tile[32][33];
    const int bz = blockIdx.z;
    const int kt = blockIdx.y;
    const int tt = blockIdx.x;
    const int tx = threadIdx.x, ty = threadIdx.y;

    int k = kt * 32 + ty;
    int t = tt * 32 + tx;
    if (t < TT)
        tile[ty][tx] = rkc[((long)bz * NKC + k) * TT + t];
    __syncthreads();
    int t2 = tt * 32 + ty;
    int k2 = kt * 32 + tx;
    if (t2 < TT)
        g_rkcT[((long)bz * TT + t2) * NKC + k2] = tile[tx][ty];
}

// ---------------------------------------------------------------------------
// R13 base (279us) + LSU balancing: wt stores deferred from post-bar1(t) to
// pre-bar1(t+1) (values persist in registers). W stores stay in D. Final wt
// slice stored after the loop. Everything else identical to R13.
// ---------------------------------------------------------------------------
// smem floats: mbar 4 | imb 40 | WrM 10000 | rkc4 3200 | r 200 | bias 100 |
//              ifbn 128 | red 80 | rdan 20 | rbdan 20 | wro 20 | wext 120
#define SM_FLOATS (4 + 40 + 10000 + 3200 + 200 + 100 + 128 + 80 + 20 + 20 + 20 + 120)

__global__ __launch_bounds__(NTHREADS, 1) __cluster_dims__(2, 1, 1)
void rnn_kernel(
    const float* __restrict__ r_ext,
    const float* __restrict__ time_arr,
    const float* __restrict__ W_kc0,
    const float* __restrict__ wt0,
    const float* __restrict__ W_recur,
    const float* __restrict__ W_readout,
    const float* __restrict__ bias,
    const float* __restrict__ W_ext,
    float* __restrict__ out)
{
    extern __shared__ float sm[];
    float* mbar_f  = sm;                  // 4
    float* imb     = sm + 4;              // 2 x 20
    float* WrM     = sm + 44;             // 100 x 100 row-major
    float* rkc4    = sm + 10044;          // 4 x 800 ring
    float* r_s     = sm + 13244;          // 2 x 100
    float* bias_s  = sm + 13444;          // 100
    float* ifbn    = sm + 13544;          // 2 x 64
    float* red_s   = sm + 13672;          // 8 slots x 10 (slot 7 stays 0)
    float* rdan_s  = sm + 13752;          // 20
    float* rbdan_s = sm + 13772;          // 20
    float* wro_s   = sm + 13792;          // 20
    float* wext_s  = sm + 13812;          // 120

    const int tid  = threadIdx.x;
    const int bx   = blockIdx.x;
    const int b    = bx >> 1;
    const int rank = bx & 1;
    const int prank = rank ^ 1;
    const int m_off = rank * 10;
    const int lane = tid & 31;
    const int warp = tid >> 5;
    const int g    = tid >> 8;
    const int q    = tid & 255;
    const bool owner = (q < 200);

    int ci2 = -1;
    bool is_loc = false, is_peer = false;
    if (warp == 7) {
        if (lane < 10)      { ci2 = m_off + lane;            is_loc  = true; }
        else if (lane < 20) { ci2 = (m_off ^ 10) + lane - 10; is_peer = true; }
        else                { ci2 = 20 + (lane - 20); }
    } else if (warp == 15) {
        if (lane < 24) ci2 = 32 + lane;
    } else if (warp == 6) {
        if (lane >= 8 && lane < 20) ci2 = 56 + (lane - 8);
    } else if (warp == 14) {
        if (lane >= 8 && lane < 20) ci2 = 68 + (lane - 8);
    }

    float* out_r  = out;
    float* out_W  = out + (long)TT * BB * NREC;
    float* out_wt = out_W + (long)TT * BB * NMBON * NKC;
    float* out_ro = out_wt + (long)TT * BB * NMBON * NKC;

    const float dt  = time_arr[1] - time_arr[0];
    const float a_r = dt;
    const float a_w = dt * 0.2f;

    const float* rkc_g = g_rkcT + (long)b * TT * NKC;

    const uint32_t imb_loc  = (uint32_t)__cvta_generic_to_shared(imb);
    const uint32_t mbar_loc = (uint32_t)__cvta_generic_to_shared(mbar_f);
    uint32_t imb_rem, mbar_rem;
    asm("mapa.shared::cluster.u32 %0, %1, %2;" : "=r"(imb_rem)  : "r"(imb_loc),  "r"(prank));
    asm("mapa.shared::cluster.u32 %0, %1, %2;" : "=r"(mbar_rem) : "r"(mbar_loc), "r"(prank));

    // ---------------- init ----------------
    if (tid == 0) {
        asm volatile("mbarrier.init.shared.b64 [%0], 10;" :: "r"(mbar_loc)     : "memory");
        asm volatile("mbarrier.init.shared.b64 [%0], 10;" :: "r"(mbar_loc + 8) : "memory");
    }
    for (int idx = tid; idx < NREC * NREC; idx += NTHREADS) {
        int i = idx / NREC, j = idx % NREC;
        float v = W_recur[idx];
        if (i < NMBON && j >= NREC - NDAN) v = 0.f;
        WrM[idx] = v;
    }
    if (tid < 80)       red_s[tid] = 0.f;
    if (tid < NREC)     bias_s[tid] = bias[tid];
    if (tid < NMBON)    wro_s[tid]  = W_readout[tid];
    if (tid >= 128 && tid < 128 + NFBN * 2) wext_s[tid - 128] = W_ext[tid - 128];
    if (tid < NREC) {
        float r0 = (tid < NMBON) ? 0.f : 0.1f;
        r_s[tid] = r0;
        if (rank == 0) out_r[(long)b * NREC + tid] = r0;
    }
    if (tid < NDAN) rbdan_s[tid] = 0.1f;
    for (int k = tid; k < NKC; k += NTHREADS)
        rkc4[k] = rkc_g[k];               // slot 0 = rkc(0)
    __syncthreads();                      // wext ready
    if (tid < NFBN) {
        float e0 = r_ext[((long)b * 2 + 0) * TT];
        float e1 = r_ext[((long)b * 2 + 1) * TT];
        ifbn[tid] = wext_s[tid * 2] * e0 + wext_s[tid * 2 + 1] * e1;
    }
    if (tid == 0 && rank == 0) out_ro[b] = 0.f;

    // owner state: W, wt, rb_kc (registers)
    float4 Wv[5], wtv[5], bkv;
    const long owner_base = ((long)b) * (NMBON * NKC) + (long)(m_off + g * 5) * NKC + q * 4;
    if (owner) {
        const long ibase = ((long)b * NMBON + m_off + g * 5) * NKC + q * 4;
#pragma unroll
        for (int mm = 0; mm < 5; ++mm) {
            float4 w  = *(const float4*)(W_kc0 + ibase + (long)mm * NKC);
            float4 wt = *(const float4*)(wt0   + ibase + (long)mm * NKC);
            Wv[mm] = w; wtv[mm] = wt;
            *(float4*)(out_W  + owner_base + (long)mm * NKC) = w;
            *(float4*)(out_wt + owner_base + (long)mm * NKC) = wt;
        }
        bkv = *(const float4*)(rkc_g + q * 4);   // rb_kc(-1) = rkc(:,0)
    } else {
#pragma unroll
        for (int mm = 0; mm < 5; ++mm) {
            Wv[mm]  = make_float4(0.f, 0.f, 0.f, 0.f);
            wtv[mm] = Wv[mm];
        }
        bkv = make_float4(0.f, 0.f, 0.f, 0.f);
    }

    // preloop prefetch: rkc(1) -> slot 1 (one committed group)
    if (warp == 15) {
        const float* gsrc = rkc_g + (long)1 * NKC;
#pragma unroll
        for (int j = 0; j < 7; ++j) {
            int c = lane + 32 * j;
            if (c < 200) {
                uint32_t dst = (uint32_t)__cvta_generic_to_shared(rkc4 + 800 + c * 4);
                asm volatile("cp.async.cg.shared.global [%0], [%1], 16;\n"
                             :: "r"(dst), "l"(gsrc + c * 4));
            }
        }
        asm volatile("cp.async.commit_group;\n" ::: "memory");
    }
    __syncthreads();
    asm volatile("barrier.cluster.arrive.aligned;" ::: "memory");
    asm volatile("barrier.cluster.wait.aligned;"   ::: "memory");

    // ---------------- time loop ----------------
    for (int t = 0; t < NSTEP; ++t) {
        const int s0  = t & 3;            // ring slot for rkc(t)
        const int hb  = t & 1;
        const int par = (t >> 1) & 1;

        const float* rc = r_s + hb * NREC;
        float* rn_buf   = r_s + (hb ^ 1) * NREC;

        // pre-bar1: deferred wt stores + B ∥ DAN-C (warp7) ∥ prefetch+ifbn+readout (warp15)
        if ((warp & 7) != 7) {
            // deferred wt store: slice t (computed at D(t-1)), skip t=0 (init wrote it)
            if (owner && t > 0) {
                float* pwt = out_wt + (long)t * (BB * NMBON * NKC) + owner_base;
#pragma unroll
                for (int mm = 0; mm < 5; ++mm)
                    *(float4*)(pwt + (long)mm * NKC) = wtv[mm];
            }
            float4 kc = make_float4(0.f, 0.f, 0.f, 0.f);
            if (owner) kc = *(const float4*)(rkc4 + s0 * 800 + q * 4);
#pragma unroll
            for (int mm = 0; mm < 5; ++mm) {
                float4 w = Wv[mm];
                float p = w.x * kc.x + w.y * kc.y + w.z * kc.z + w.w * kc.w;
                p += __shfl_xor_sync(0xffffffffu, p, 16);
                p += __shfl_xor_sync(0xffffffffu, p, 8);
                p += __shfl_xor_sync(0xffffffffu, p, 4);
                p += __shfl_xor_sync(0xffffffffu, p, 2);
                p += __shfl_xor_sync(0xffffffffu, p, 1);
                if (lane == 0)
                    red_s[(warp & 7) * 10 + g * 5 + mm] = p;
            }
        } else if (warp == 7) {
            if (lane < NDAN) {
                const int i = 80 + lane;
                const float4* wrow = (const float4*)(WrM + i * NREC);
                const float4* r4   = (const float4*)rc;
                float a0 = 0.f, a1 = 0.f, a2 = 0.f, a3 = 0.f;
#pragma unroll
                for (int jb = 0; jb < 25; ++jb) {
                    float4 wv = wrow[jb];
                    float4 rv = r4[jb];
                    a0 = fmaf(wv.x, rv.x, a0);
                    a1 = fmaf(wv.y, rv.y, a1);
                    a2 = fmaf(wv.z, rv.z, a2);
                    a3 = fmaf(wv.w, rv.w, a3);
                }
                float pre  = (a0 + a1) + (a2 + a3) + bias_s[i];
                float relu = fmaxf(pre, 0.f);
                float rold = rc[i];
                float rn   = fmaf(a_r, relu - rold, rold);
                rn_buf[i] = rn;
                if (rank == 0) out_r[((long)(t + 1) * BB + b) * NREC + i] = rn;
                rdan_s[lane] = rn;
                float rb = rbdan_s[lane];
                rbdan_s[lane] = fmaf(a_w, rn - rb, rb);
            }
        } else {
            // warp 15: distance-2 prefetch rkc(t+2), ifbn(t+1), readout(t)
            if (t + 2 <= NSTEP - 1) {
                const float* gsrc = rkc_g + (long)(t + 2) * NKC;
                const int sw = (t + 2) & 3;
#pragma unroll
                for (int j = 0; j < 7; ++j) {
                    int c = lane + 32 * j;
                    if (c < 200) {
                        uint32_t dst = (uint32_t)__cvta_generic_to_shared(rkc4 + sw * 800 + c * 4);
                        asm volatile("cp.async.cg.shared.global [%0], [%1], 16;\n"
                                     :: "r"(dst), "l"(gsrc + c * 4));
                    }
                }
            }
            asm volatile("cp.async.commit_group;\n" ::: "memory");   // possibly empty
            float e0 = r_ext[((long)b * 2 + 0) * TT + (t + 1)];
            float e1 = r_ext[((long)b * 2 + 1) * TT + (t + 1)];
            {
                int f = lane;
                ifbn[(hb ^ 1) * 64 + f] = wext_s[f * 2] * e0 + wext_s[f * 2 + 1] * e1;
                f = lane + 32;
                if (f < NFBN)
                    ifbn[(hb ^ 1) * 64 + f] = wext_s[f * 2] * e0 + wext_s[f * 2 + 1] * e1;
            }
            if (lane == 24 && rank == 0 && t > 0) {
                // readout(t) from r(t); out_ro[0] written in init (= 0)
                float v = 0.f;
#pragma unroll
                for (int m = 0; m < NMBON; ++m)
                    v = fmaf(rc[m], wro_s[m], v);
                out_ro[(long)t * BB + b] = v;
            }
        }
        __syncthreads();   // bar1: red_s, rdan/rbdan(t), ifbn(t+1) ready

        // post-bar1: send FIRST, then D (owners, W stores only) ∥ C dots ∥ cp wait
        float vloc = 0.f;
        if (warp == 7 && lane < 10) {
            vloc = red_s[0 * 10 + lane] + red_s[1 * 10 + lane] + red_s[2 * 10 + lane]
                 + red_s[3 * 10 + lane] + red_s[4 * 10 + lane] + red_s[5 * 10 + lane]
                 + red_s[6 * 10 + lane];
            asm volatile("st.shared::cluster.f32 [%0], %1;"
                         :: "r"(imb_rem + (hb * 20 + m_off + lane) * 4), "f"(vloc) : "memory");
            asm volatile("mbarrier.arrive.release.cluster.shared::cluster.b64 _, [%0];"
                         :: "r"(mbar_rem + hb * 8) : "memory");
        }

        if (owner) {
            // D(t): rb_kc EMA in registers + plasticity; store W only (wt deferred)
            float4 kc = *(const float4*)(rkc4 + s0 * 800 + q * 4);
            bkv.x = fmaf(a_w, kc.x - bkv.x, bkv.x);
            bkv.y = fmaf(a_w, kc.y - bkv.y, bkv.y);
            bkv.z = fmaf(a_w, kc.z - bkv.z, bkv.z);
            bkv.w = fmaf(a_w, kc.w - bkv.w, bkv.w);
            float* pW = out_W + (long)(t + 1) * (BB * NMBON * NKC) + owner_base;
#pragma unroll
            for (int mm = 0; mm < 5; ++mm) {
                const int m = m_off + g * 5 + mm;
                const float rbd = rbdan_s[m];
                const float rd  = rdan_s[m];
                float4 w = Wv[mm], wt = wtv[mm];
                float dw;
                dw = fmaf(rbd, kc.x, -(rd * bkv.x)); wt.x = fmaf(dw, dt, wt.x);
                dw = fmaf(rbd, kc.y, -(rd * bkv.y)); wt.y = fmaf(dw, dt, wt.y);
                dw = fmaf(rbd, kc.z, -(rd * bkv.z)); wt.z = fmaf(dw, dt, wt.z);
                dw = fmaf(rbd, kc.w, -(rd * bkv.w)); wt.w = fmaf(dw, dt, wt.w);
                w.x = fminf(fmaxf(fmaf(a_w, wt.x - w.x, w.x), 0.f), W_MAXC);
                w.y = fminf(fmaxf(fmaf(a_w, wt.y - w.y, w.y), 0.f), W_MAXC);
                w.z = fminf(fmaxf(fmaf(a_w, wt.z - w.z, w.z), 0.f), W_MAXC);
                w.w = fminf(fmaxf(fmaf(a_w, wt.w - w.w, w.w), 0.f), W_MAXC);
                Wv[mm] = w; wtv[mm] = wt;
                *(float4*)(pW + (long)mm * NKC) = w;
            }
        }

        if (ci2 >= 0) {
            const int i = ci2;
            const float4* wrow = (const float4*)(WrM + i * NREC);
            const float4* r4   = (const float4*)rc;
            float a0 = 0.f, a1 = 0.f, a2 = 0.f, a3 = 0.f;
#pragma unroll
            for (int jb = 0; jb < 25; ++jb) {
                float4 wv = wrow[jb];
                float4 rv = r4[jb];
                a0 = fmaf(wv.x, rv.x, a0);
                a1 = fmaf(wv.y, rv.y, a1);
                a2 = fmaf(wv.z, rv.z, a2);
                a3 = fmaf(wv.w, rv.w, a3);
            }
            float p = (a0 + a1) + (a2 + a3);
            float itot;
            if (is_loc) {
                itot = vloc;
            } else if (is_peer) {
                uint32_t done;
                asm volatile(
                    "{\n\t.reg .pred p;\n\t"
                    "mbarrier.try_wait.parity.acquire.cluster.shared::cta.b64 p, [%1], %2;\n\t"
                    "selp.b32 %0, 1, 0, p;\n\t}"
                    : "=r"(done) : "r"(mbar_loc + hb * 8), "r"(par) : "memory");
                while (!done) {
                    asm volatile(
                        "{\n\t.reg .pred p;\n\t"
                        "mbarrier.try_wait.parity.acquire.cluster.shared::cta.b64 p, [%1], %2, 0x989680;\n\t"
                        "selp.b32 %0, 1, 0, p;\n\t}"
                        : "=r"(done) : "r"(mbar_loc + hb * 8), "r"(par) : "memory");
                }
                itot = imb[hb * 20 + i];
            } else {
                itot = ifbn[hb * 64 + (i - NMBON)];
            }
            float pre  = p + bias_s[i] + itot;
            float relu = fmaxf(pre, 0.f);
            float rold = rc[i];
            float rn   = fmaf(a_r, relu - rold, rold);
            rn_buf[i] = rn;
            if (rank == 0) out_r[((long)(t + 1) * BB + b) * NREC + i] = rn;
        }

        if (warp == 15)
            asm volatile("cp.async.wait_group 1;\n" ::: "memory");   // rkc(t+1) ready

        __syncthreads();   // bar2
    }

    // tail: final deferred wt slice (t = NSTEP) + final readout
    if (owner) {
        float* pwt = out_wt + (long)NSTEP * (BB * NMBON * NKC) + owner_base;
#pragma unroll
        for (int mm = 0; mm < 5; ++mm)
            *(float4*)(pwt + (long)mm * NKC) = wtv[mm];
    }
    if (warp == 15 && lane == 24 && rank == 0) {
        float v = 0.f;
#pragma unroll
        for (int m = 0; m < NMBON; ++m)
            v = fmaf(r_s[m], wro_s[m], v);
        out_ro[(long)NSTEP * BB + b] = v;
    }

    asm volatile("barrier.cluster.arrive.aligned;" ::: "memory");
    asm volatile("barrier.cluster.wait.aligned;"   ::: "memory");
}

// ---------------------------------------------------------------------------
extern "C" void kernel_launch(void* const* d_in, const int* in_sizes, int n_in,
                              void* d_out, int out_size) {
    const float* r_kc      = (const float*)d_in[0];
    const float* r_ext     = (const float*)d_in[1];
    const float* time_arr  = (const float*)d_in[2];
    const float* W_kc0     = (const float*)d_in[3];
    const float* wt0       = (const float*)d_in[4];
    const float* W_recur   = (const float*)d_in[5];
    const float* W_readout = (const float*)d_in[6];
    const float* bias      = (const float*)d_in[7];
    const float* W_ext     = (const float*)d_in[8];
    float* out = (float*)d_out;

    cudaFuncSetAttribute(rnn_kernel, cudaFuncAttributeMaxDynamicSharedMemorySize,
                         SM_FLOATS * (int)sizeof(float));

    transpose_kernel<<<dim3(4, 25, BB), dim3(32, 32)>>>(r_kc);
    rnn_kernel<<<NCTA, NTHREADS, SM_FLOATS * (int)sizeof(float)>>>(
        r_ext, time_arr, W_kc0, wt0, W_recur, W_readout, bias, W_ext, out);
}